// round 2
// baseline (speedup 1.0000x reference)
#include <cuda_runtime.h>

#define N_ELEMS 8388608
#define DEGREE 8

// Inverse factorials 1/d! for d = 0..7 (compile-time constants)
__device__ __constant__ const float kInvFact[DEGREE] = {
    1.0f,                    // 1/0!
    1.0f,                    // 1/1!
    0.5f,                    // 1/2!
    1.0f / 6.0f,             // 1/3!
    1.0f / 24.0f,            // 1/4!
    1.0f / 120.0f,           // 1/5!
    1.0f / 720.0f,           // 1/6!
    1.0f / 5040.0f           // 1/7!
};

__global__ __launch_bounds__(256)
void poly_kernel(const float* __restrict__ X,
                 const float* __restrict__ w,
                 const float* __restrict__ b,
                 float* __restrict__ out,
                 int n4)  // number of float4 elements
{
    // Fold coefficients: c[d] = w[d] / d!   (w is tiny; hits L1/L2, broadcast)
    float c0 = __ldg(&w[0]) * kInvFact[0];
    float c1 = __ldg(&w[1]) * kInvFact[1];
    float c2 = __ldg(&w[2]) * kInvFact[2];
    float c3 = __ldg(&w[3]) * kInvFact[3];
    float c4 = __ldg(&w[4]) * kInvFact[4];
    float c5 = __ldg(&w[5]) * kInvFact[5];
    float c6 = __ldg(&w[6]) * kInvFact[6];
    float c7 = __ldg(&w[7]) * kInvFact[7];
    float bias = __ldg(&b[0]);
    c0 += bias;  // fold bias into the constant term

    const float4* __restrict__ X4 = reinterpret_cast<const float4*>(X);
    float4* __restrict__ out4 = reinterpret_cast<float4*>(out);

    int idx = blockIdx.x * blockDim.x + threadIdx.x;
    int stride = gridDim.x * blockDim.x;

    for (int i = idx; i < n4; i += stride) {
        float4 x = X4[i];
        float4 r;

        // Horner: r = (((((((c7*x + c6)*x + c5)*x + c4)*x + c3)*x + c2)*x + c1)*x + c0)
        {
            float v = x.x;
            float a = fmaf(c7, v, c6);
            a = fmaf(a, v, c5);
            a = fmaf(a, v, c4);
            a = fmaf(a, v, c3);
            a = fmaf(a, v, c2);
            a = fmaf(a, v, c1);
            r.x = fmaf(a, v, c0);
        }
        {
            float v = x.y;
            float a = fmaf(c7, v, c6);
            a = fmaf(a, v, c5);
            a = fmaf(a, v, c4);
            a = fmaf(a, v, c3);
            a = fmaf(a, v, c2);
            a = fmaf(a, v, c1);
            r.y = fmaf(a, v, c0);
        }
        {
            float v = x.z;
            float a = fmaf(c7, v, c6);
            a = fmaf(a, v, c5);
            a = fmaf(a, v, c4);
            a = fmaf(a, v, c3);
            a = fmaf(a, v, c2);
            a = fmaf(a, v, c1);
            r.z = fmaf(a, v, c0);
        }
        {
            float v = x.w;
            float a = fmaf(c7, v, c6);
            a = fmaf(a, v, c5);
            a = fmaf(a, v, c4);
            a = fmaf(a, v, c3);
            a = fmaf(a, v, c2);
            a = fmaf(a, v, c1);
            r.w = fmaf(a, v, c0);
        }

        out4[i] = r;
    }
}

extern "C" void kernel_launch(void* const* d_in, const int* in_sizes, int n_in,
                              void* d_out, int out_size)
{
    const float* X = (const float*)d_in[0];
    const float* w = (const float*)d_in[1];
    const float* b = (const float*)d_in[2];
    float* out = (float*)d_out;

    int n = in_sizes[0];        // 8388608, divisible by 4
    int n4 = n / 4;             // 2097152 float4 elements

    const int threads = 256;
    int blocks = (n4 + threads - 1) / threads;   // 8192 blocks — one pass

    poly_kernel<<<blocks, threads>>>(X, w, b, out, n4);
}